// round 1
// baseline (speedup 1.0000x reference)
#include <cuda_runtime.h>
#include <math.h>

#define FEAT 1040
#define NHEADS 8
#define DHEAD 130
#define NNODES 30000
#define MAXEDGES 240000
#define NE2MAX (MAXEDGES + NNODES)
#define NGRAPHS 64
#define NEG_SLOPE 0.2f
#define BN_EPS 1e-5f

// ---------------- scratch (device globals; no allocation allowed) ----------------
__device__ float g_xh[NNODES * FEAT];     // per-layer transformed features
__device__ float g_att[NNODES * FEAT];    // attention aggregation output
__device__ float g_h0[NNODES * FEAT];     // feature ping
__device__ float g_h1[NNODES * FEAT];     // feature pong
__device__ float g_as[NNODES * NHEADS];   // alpha_src per node/head
__device__ float g_ad[NNODES * NHEADS];   // alpha_dst per node/head
__device__ unsigned int g_emax[NNODES * NHEADS]; // segment max (monotone uint keys)
__device__ float g_denom[NNODES * NHEADS];
__device__ float g_ex[NE2MAX * NHEADS];   // exp(e - max) per edge/head
__device__ float g_pooled[NGRAPHS * FEAT];
__device__ float g_counts[NGRAPHS];

// ---------------- helpers ----------------
__device__ __forceinline__ unsigned int f2key(float v) {
    unsigned int u = __float_as_uint(v);
    return (u & 0x80000000u) ? ~u : (u | 0x80000000u);
}
__device__ __forceinline__ float key2f(unsigned int k) {
    return (k & 0x80000000u) ? __uint_as_float(k ^ 0x80000000u) : __uint_as_float(~k);
}

__global__ void zero_f32(float* p, int n) {
    int i = blockIdx.x * blockDim.x + threadIdx.x;
    if (i < n) p[i] = 0.0f;
}
__global__ void zero_u32(unsigned int* p, int n) {
    int i = blockIdx.x * blockDim.x + threadIdx.x;
    if (i < n) p[i] = 0u;
}

// ---------------- GEMM: C[M,N] = A[M,K] @ B[K,N] (fp32, 128x64x16, 8x4/thread) --------
#define BM 128
#define BN 64
#define BK 16
__global__ __launch_bounds__(256) void sgemm_kernel(
    const float* __restrict__ A, const float* __restrict__ B, float* __restrict__ C,
    int M, int N, int K)
{
    __shared__ float As[BK][BM];
    __shared__ float Bs[BK][BN];
    int tid = threadIdx.x;
    int tx = tid & 15;        // col group: 4 cols
    int ty = tid >> 4;        // row group: 8 rows
    int row0 = blockIdx.y * BM;
    int col0 = blockIdx.x * BN;

    float acc[8][4];
#pragma unroll
    for (int i = 0; i < 8; i++)
#pragma unroll
        for (int j = 0; j < 4; j++) acc[i][j] = 0.0f;

    for (int k0 = 0; k0 < K; k0 += BK) {
        // A: 128x16 = 2048 floats = 512 float4, 2 per thread; stored transposed
#pragma unroll
        for (int it = 0; it < 2; it++) {
            int lin = tid + it * 256;           // 0..511
            int ar = lin >> 2;                  // 0..127
            int ac = (lin & 3) * 4;             // 0,4,8,12
            int gr = row0 + ar;
            float4 v = make_float4(0.f, 0.f, 0.f, 0.f);
            if (gr < M) v = *(const float4*)&A[(size_t)gr * K + k0 + ac];
            As[ac + 0][ar] = v.x;
            As[ac + 1][ar] = v.y;
            As[ac + 2][ar] = v.z;
            As[ac + 3][ar] = v.w;
        }
        // B: 16x64 = 1024 floats = 256 float4, 1 per thread
        {
            int br = tid >> 4;                  // 0..15
            int bc = (tid & 15) * 4;            // 0..60
            int gc = col0 + bc;
            float4 v = make_float4(0.f, 0.f, 0.f, 0.f);
            if (gc < N) v = *(const float4*)&B[(size_t)(k0 + br) * N + gc];
            Bs[br][bc + 0] = v.x;
            Bs[br][bc + 1] = v.y;
            Bs[br][bc + 2] = v.z;
            Bs[br][bc + 3] = v.w;
        }
        __syncthreads();
#pragma unroll
        for (int k = 0; k < BK; k++) {
            float4 a0 = *(const float4*)&As[k][ty * 8];
            float4 a1 = *(const float4*)&As[k][ty * 8 + 4];
            float4 bb = *(const float4*)&Bs[k][tx * 4];
            float a[8] = {a0.x, a0.y, a0.z, a0.w, a1.x, a1.y, a1.z, a1.w};
            float b[4] = {bb.x, bb.y, bb.z, bb.w};
#pragma unroll
            for (int i = 0; i < 8; i++)
#pragma unroll
                for (int j = 0; j < 4; j++) acc[i][j] = fmaf(a[i], b[j], acc[i][j]);
        }
        __syncthreads();
    }
#pragma unroll
    for (int i = 0; i < 8; i++) {
        int r = row0 + ty * 8 + i;
        if (r >= M) continue;
#pragma unroll
        for (int j = 0; j < 4; j++) {
            int c = col0 + tx * 4 + j;
            if (c < N) C[(size_t)r * N + c] = acc[i][j];
        }
    }
}

// ---------------- alpha_src / alpha_dst: per (node, head) dot over d ----------------
__global__ void alpha_kernel(const float* __restrict__ xh,
                             const float* __restrict__ a_src,
                             const float* __restrict__ a_dst,
                             float* __restrict__ out_s, float* __restrict__ out_d)
{
    int n = blockIdx.x;
    int h = threadIdx.x >> 5;     // warp = head (8 warps)
    int lane = threadIdx.x & 31;
    const float* row = xh + (size_t)n * FEAT + h * DHEAD;
    const float* vs = a_src + h * DHEAD;
    const float* vd = a_dst + h * DHEAD;
    float s1 = 0.f, s2 = 0.f;
    for (int i = lane; i < DHEAD; i += 32) {
        float v = row[i];
        s1 = fmaf(v, vs[i], s1);
        s2 = fmaf(v, vd[i], s2);
    }
#pragma unroll
    for (int o = 16; o; o >>= 1) {
        s1 += __shfl_xor_sync(0xFFFFFFFFu, s1, o);
        s2 += __shfl_xor_sync(0xFFFFFFFFu, s2, o);
    }
    if (lane == 0) {
        out_s[n * NHEADS + h] = s1;
        out_d[n * NHEADS + h] = s2;
    }
}

// ---------------- edge pass A: segment max ----------------
__global__ void edge_max_kernel(const int* __restrict__ src, const int* __restrict__ dst,
                                int E, const float* __restrict__ as_,
                                const float* __restrict__ ad_, unsigned int* __restrict__ emax)
{
    int idx = blockIdx.x * blockDim.x + threadIdx.x;
    int total = (E + NNODES) * NHEADS;
    if (idx >= total) return;
    int e = idx >> 3;
    int h = idx & 7;
    int s, d;
    if (e < E) { s = src[e]; d = dst[e]; }
    else       { s = e - E; d = s; }
    float v = as_[s * NHEADS + h] + ad_[d * NHEADS + h];
    v = (v > 0.f) ? v : NEG_SLOPE * v;
    atomicMax(&emax[d * NHEADS + h], f2key(v));
}

// ---------------- edge pass B: exp + denom ----------------
__global__ void edge_exp_kernel(const int* __restrict__ src, const int* __restrict__ dst,
                                int E, const float* __restrict__ as_,
                                const float* __restrict__ ad_,
                                const unsigned int* __restrict__ emax,
                                float* __restrict__ exbuf, float* __restrict__ denom)
{
    int idx = blockIdx.x * blockDim.x + threadIdx.x;
    int total = (E + NNODES) * NHEADS;
    if (idx >= total) return;
    int e = idx >> 3;
    int h = idx & 7;
    int s, d;
    if (e < E) { s = src[e]; d = dst[e]; }
    else       { s = e - E; d = s; }
    float v = as_[s * NHEADS + h] + ad_[d * NHEADS + h];
    v = (v > 0.f) ? v : NEG_SLOPE * v;
    float m = key2f(emax[d * NHEADS + h]);
    float ex = expf(v - m);
    exbuf[idx] = ex;
    atomicAdd(&denom[d * NHEADS + h], ex);
}

// ---------------- edge pass C: weighted scatter ----------------
__global__ __launch_bounds__(256) void edge_scatter_kernel(
    const int* __restrict__ src, const int* __restrict__ dst, int E,
    const float* __restrict__ xh, const float* __restrict__ exbuf,
    const float* __restrict__ denom, float* __restrict__ att)
{
    int e = blockIdx.x;
    int s, d;
    if (e < E) { s = src[e]; d = dst[e]; }
    else       { s = e - E; d = s; }
    __shared__ float alpha[NHEADS];
    if (threadIdx.x < NHEADS)
        alpha[threadIdx.x] = exbuf[e * NHEADS + threadIdx.x] / denom[d * NHEADS + threadIdx.x];
    __syncthreads();
    const float* xrow = xh + (size_t)s * FEAT;
    float* orow = att + (size_t)d * FEAT;
    for (int c = threadIdx.x; c < FEAT; c += 256) {
        int h = c / DHEAD;
        atomicAdd(&orow[c], alpha[h] * xrow[c]);
    }
}

// ---------------- BN(eval) + bias + residual + relu ----------------
__global__ void bn_kernel(const float* __restrict__ att, const float* __restrict__ prev,
                          const float* __restrict__ b_att, const float* __restrict__ gamma,
                          const float* __restrict__ beta, const float* __restrict__ mean,
                          const float* __restrict__ var, float* __restrict__ out)
{
    int idx = blockIdx.x * blockDim.x + threadIdx.x;
    if (idx >= NNODES * FEAT) return;
    int c = idx % FEAT;
    float z = att[idx] + b_att[c];
    if (prev) z += prev[idx];
    z = (z - mean[c]) * rsqrtf(var[c] + BN_EPS) * gamma[c] + beta[c];
    out[idx] = (z > 0.f) ? z : 0.f;
}

// ---------------- pooling ----------------
__global__ void count_kernel(const int* __restrict__ batch, int N) {
    int n = blockIdx.x * blockDim.x + threadIdx.x;
    if (n < N) atomicAdd(&g_counts[batch[n]], 1.0f);
}
__global__ void pool_kernel(const int* __restrict__ batch, const float* __restrict__ h, int N) {
    int idx = blockIdx.x * blockDim.x + threadIdx.x;
    if (idx >= N * FEAT) return;
    int n = idx / FEAT;
    int c = idx - n * FEAT;
    atomicAdd(&g_pooled[batch[n] * FEAT + c], h[idx]);
}

// ---------------- final head: out[g, :2] = (pooled/cnt) @ W_out + b_out ----------------
__global__ void head_kernel(const float* __restrict__ W_out, const float* __restrict__ b_out,
                            float* __restrict__ out)
{
    int g = blockIdx.x;
    int tid = threadIdx.x;  // 128 threads
    float cnt = fmaxf(g_counts[g], 1.0f);
    float inv = 1.0f / cnt;
    float s0 = 0.f, s1 = 0.f;
    for (int c = tid; c < FEAT; c += 128) {
        float p = g_pooled[g * FEAT + c] * inv;
        s0 = fmaf(p, W_out[2 * c + 0], s0);
        s1 = fmaf(p, W_out[2 * c + 1], s1);
    }
#pragma unroll
    for (int o = 16; o; o >>= 1) {
        s0 += __shfl_xor_sync(0xFFFFFFFFu, s0, o);
        s1 += __shfl_xor_sync(0xFFFFFFFFu, s1, o);
    }
    __shared__ float r0[4], r1[4];
    if ((tid & 31) == 0) { r0[tid >> 5] = s0; r1[tid >> 5] = s1; }
    __syncthreads();
    if (tid == 0) {
        out[g * 2 + 0] = r0[0] + r0[1] + r0[2] + r0[3] + b_out[0];
        out[g * 2 + 1] = r1[0] + r1[1] + r1[2] + r1[3] + b_out[1];
    }
}

// ---------------- host launcher ----------------
extern "C" void kernel_launch(void* const* d_in, const int* in_sizes, int n_in,
                              void* d_out, int out_size)
{
    const float* x        = (const float*)d_in[0];
    const int*   edge_idx = (const int*)  d_in[1];
    const int*   batch    = (const int*)  d_in[2];
    const float* W        = (const float*)d_in[3];   // [3,1040,8,130]
    const float* a_src    = (const float*)d_in[4];   // [3,8,130]
    const float* a_dst    = (const float*)d_in[5];
    const float* b_att    = (const float*)d_in[6];   // [3,1040]
    const float* gamma    = (const float*)d_in[7];
    const float* beta     = (const float*)d_in[8];
    const float* run_mean = (const float*)d_in[9];
    const float* run_var  = (const float*)d_in[10];
    const float* W_out    = (const float*)d_in[11];  // [1040,2]
    const float* b_out    = (const float*)d_in[12];
    float* out = (float*)d_out;

    int N = in_sizes[0] / FEAT;          // 30000
    int E = in_sizes[1] / 2;             // 240000
    const int* src = edge_idx;
    const int* dst = edge_idx + E;
    int E2 = E + N;

    float *p_xh, *p_att, *p_h0, *p_h1, *p_as, *p_ad, *p_denom, *p_ex, *p_pooled, *p_counts;
    unsigned int* p_emax;
    cudaGetSymbolAddress((void**)&p_xh, g_xh);
    cudaGetSymbolAddress((void**)&p_att, g_att);
    cudaGetSymbolAddress((void**)&p_h0, g_h0);
    cudaGetSymbolAddress((void**)&p_h1, g_h1);
    cudaGetSymbolAddress((void**)&p_as, g_as);
    cudaGetSymbolAddress((void**)&p_ad, g_ad);
    cudaGetSymbolAddress((void**)&p_emax, g_emax);
    cudaGetSymbolAddress((void**)&p_denom, g_denom);
    cudaGetSymbolAddress((void**)&p_ex, g_ex);
    cudaGetSymbolAddress((void**)&p_pooled, g_pooled);
    cudaGetSymbolAddress((void**)&p_counts, g_counts);

    dim3 gemm_grid((FEAT + BN - 1) / BN, (N + BM - 1) / BM);
    int nf = N * FEAT;
    int nh = N * NHEADS;
    int eh = E2 * NHEADS;

    const float* layer_in[3]  = {x, p_h0, p_h1};
    const float* layer_prev[3] = {nullptr, x, p_h0};
    float*       layer_out[3] = {p_h0, p_h1, p_h0};   // l2: in-place over prev (elementwise, safe)

    for (int l = 0; l < 3; l++) {
        const float* Wl = W + (size_t)l * FEAT * FEAT;
        // 1. xh = h @ W[l]
        sgemm_kernel<<<gemm_grid, 256>>>(layer_in[l], Wl, p_xh, N, FEAT, FEAT);
        // 2. alpha_src / alpha_dst
        alpha_kernel<<<N, 256>>>(p_xh, a_src + l * NHEADS * DHEAD, a_dst + l * NHEADS * DHEAD,
                                 p_as, p_ad);
        // 3. clear segment buffers + att accumulator
        zero_u32<<<(nh + 255) / 256, 256>>>(p_emax, nh);
        zero_f32<<<(nh + 255) / 256, 256>>>(p_denom, nh);
        zero_f32<<<(nf + 255) / 256, 256>>>(p_att, nf);
        // 4. softmax passes
        edge_max_kernel<<<(eh + 255) / 256, 256>>>(src, dst, E, p_as, p_ad, p_emax);
        edge_exp_kernel<<<(eh + 255) / 256, 256>>>(src, dst, E, p_as, p_ad, p_emax, p_ex, p_denom);
        edge_scatter_kernel<<<E2, 256>>>(src, dst, E, p_xh, p_ex, p_denom, p_att);
        // 5. residual + BN + relu
        bn_kernel<<<(nf + 255) / 256, 256>>>(p_att, layer_prev[l], b_att + l * FEAT,
                                             gamma + l * FEAT, beta + l * FEAT,
                                             run_mean + l * FEAT, run_var + l * FEAT,
                                             layer_out[l]);
    }

    // global mean pool + head
    zero_f32<<<(NGRAPHS * FEAT + 255) / 256, 256>>>(p_pooled, NGRAPHS * FEAT);
    zero_f32<<<1, NGRAPHS>>>(p_counts, NGRAPHS);
    count_kernel<<<(N + 255) / 256, 256>>>(batch, N);
    pool_kernel<<<(nf + 255) / 256, 256>>>(batch, layer_out[2], N);
    head_kernel<<<NGRAPHS, 128>>>(W_out, b_out, out);
}